// round 1
// baseline (speedup 1.0000x reference)
#include <cuda_runtime.h>
#include <math.h>

// Problem constants (fixed shapes)
#define B      64
#define EMB    1024
#define WID    64
#define MODES  16
#define LSEQ   8192
#define LOUT   8190       // LSEQ - PADDING(2)
#define NH     128        // hidden width of MLP
#define DECM   2048       // WID*MODES*2

// Scratch (allocation-free rule: use __device__ globals)
__device__ float  g_H[B * DECM];          // token @ w_dec + b_dec   [B][WID][MODES][2]
__device__ float4 g_R[B * NH * 8];        // interleaved (P,Q) coeffs [B][128 j][16k*2] as float4

// ---------------------------------------------------------------------------
// Kernel 1: H = token @ w_dec + b_dec     (64x2048, K=1024)
// grid (16 m-tiles, 8 b-tiles), 128 threads; 8 b-accumulators per thread
// ---------------------------------------------------------------------------
__global__ void __launch_bounds__(128) fno_decode_gemm(
    const float* __restrict__ token,   // [B][EMB]
    const float* __restrict__ wdec,    // [EMB][DECM]
    const float* __restrict__ bdec)    // [DECM]
{
    __shared__ float ts[8][32];
    const int m  = blockIdx.x * 128 + threadIdx.x;
    const int b0 = blockIdx.y * 8;

    float acc[8];
#pragma unroll
    for (int i = 0; i < 8; i++) acc[i] = 0.f;

    for (int e0 = 0; e0 < EMB; e0 += 32) {
        for (int i = threadIdx.x; i < 256; i += 128) {
            int bb = i >> 5, ee = i & 31;
            ts[bb][ee] = token[(b0 + bb) * EMB + e0 + ee];
        }
        __syncthreads();
#pragma unroll 8
        for (int ee = 0; ee < 32; ee++) {
            float w = wdec[(e0 + ee) * DECM + m];
#pragma unroll
            for (int bb = 0; bb < 8; bb++)
                acc[bb] = fmaf(ts[bb][ee], w, acc[bb]);
        }
        __syncthreads();
    }
    float bd = bdec[m];
#pragma unroll
    for (int bb = 0; bb < 8; bb++)
        g_H[(b0 + bb) * DECM + m] = acc[bb] + bd;
}

// ---------------------------------------------------------------------------
// Kernel 2: build spectral->hidden coefficients
//   P[b,j,k] =  sA(k) * sum_w w1[w,j] * H[b,w,k,re]
//   Q[b,j,k] =  sB(k) * sum_w w1[w,j] * H[b,w,k,im]
//   sA = 1/n (k=0) else 2/n ;  sB = 0 (k=0) else -2/n
// stored interleaved: R[b][j][2k]=P, [2k+1]=Q  (float4-friendly)
// grid 64 (one b), 256 threads
// ---------------------------------------------------------------------------
__global__ void __launch_bounds__(256) fno_build_R(
    const float* __restrict__ w1)      // [WID][NH]
{
    __shared__ float w1s[WID * NH];    // 32 KB
    __shared__ float Hs[DECM];         // 8 KB  ([w][k][2])
    const int b = blockIdx.x;

    for (int i = threadIdx.x; i < WID * NH; i += 256) w1s[i] = w1[i];
    for (int i = threadIdx.x; i < DECM;     i += 256) Hs[i]  = g_H[b * DECM + i];
    __syncthreads();

    const float inv = 1.0f / (float)LSEQ;
    float* Rf = (float*)g_R;

    for (int c = threadIdx.x; c < NH * MODES; c += 256) {
        int j = c >> 4;
        int k = c & 15;
        float P = 0.f, Q = 0.f;
#pragma unroll 8
        for (int w = 0; w < WID; w++) {
            float a = w1s[w * NH + j];
            P = fmaf(a, Hs[w * 32 + 2 * k],     P);
            Q = fmaf(a, Hs[w * 32 + 2 * k + 1], Q);
        }
        float sA = (k == 0) ? inv : 2.0f * inv;
        float sB = (k == 0) ? 0.f : -2.0f * inv;
        Rf[(b * NH + j) * 32 + 2 * k]     = sA * P;
        Rf[(b * NH + j) * 32 + 2 * k + 1] = sB * Q;
    }
}

// ---------------------------------------------------------------------------
// Kernel 3 (hot): per output position l
//   h1[j] = b1[j] + sum_k P[j,k] cos(th_k l) + Q[j,k] sin(th_k l)
//   out   = b2 + sum_j gelu_erf(h1[j]) * w2[j]
// One l per thread; coefficients broadcast from shared via LDS.128.
// grid (32 l-chunks, 64 b), 256 threads
// ---------------------------------------------------------------------------
__global__ void __launch_bounds__(256) fno_main(
    const float* __restrict__ b1,
    const float* __restrict__ w2,
    const float* __restrict__ b2,
    float* __restrict__ out)
{
    __shared__ float4 Rs[NH * 8];      // 16 KB
    __shared__ float  b1s[NH], w2s[NH];

    const int b = blockIdx.y;
    const float4* Rg = g_R + b * NH * 8;
    for (int i = threadIdx.x; i < NH * 8; i += 256) Rs[i] = Rg[i];
    if (threadIdx.x < NH) {
        b1s[threadIdx.x] = b1[threadIdx.x];
        w2s[threadIdx.x] = w2[threadIdx.x];
    }
    __syncthreads();

    const int l = blockIdx.x * 256 + threadIdx.x;
    if (l >= LOUT) return;

    // cos/sin of th_k*l, k=0..15, via one sincos + Chebyshev recurrence
    float c[MODES], s[MODES];
    float ang = (float)l * 7.6699039394282067e-4f;   // 2*pi/8192
    float s1, c1;
    sincosf(ang, &s1, &c1);
    c[0] = 1.f; s[0] = 0.f;
    c[1] = c1;  s[1] = s1;
    const float t2 = 2.f * c1;
#pragma unroll
    for (int k = 2; k < MODES; k++) {
        c[k] = fmaf(t2, c[k - 1], -c[k - 2]);
        s[k] = fmaf(t2, s[k - 1], -s[k - 2]);
    }

    float acc = 0.f;
#pragma unroll 2
    for (int j = 0; j < NH; j++) {
        float h = b1s[j];
        const float4* rj = &Rs[j * 8];
#pragma unroll
        for (int kp = 0; kp < 8; kp++) {
            float4 r = rj[kp];                    // broadcast LDS.128
            h = fmaf(r.x, c[2 * kp],     h);
            h = fmaf(r.y, s[2 * kp],     h);
            h = fmaf(r.z, c[2 * kp + 1], h);
            h = fmaf(r.w, s[2 * kp + 1], h);
        }
        // exact gelu: 0.5*h*(1+erf(h/sqrt(2)))
        float g = 0.5f * h * (1.0f + erff(h * 0.70710678118654752f));
        acc = fmaf(g, w2s[j], acc);
    }
    out[b * LOUT + l] = acc + b2[0];
}

// ---------------------------------------------------------------------------
extern "C" void kernel_launch(void* const* d_in, const int* in_sizes, int n_in,
                              void* d_out, int out_size)
{
    // inputs: token, [x_len], w_dec, b_dec, w1, b1, w2, b2
    const float* token = (const float*)d_in[0];
    int wi = (in_sizes[1] < 100) ? 2 : 1;   // skip x_len scalar if present
    const float* wdec = (const float*)d_in[wi + 0];
    const float* bdec = (const float*)d_in[wi + 1];
    const float* w1   = (const float*)d_in[wi + 2];
    const float* b1   = (const float*)d_in[wi + 3];
    const float* w2   = (const float*)d_in[wi + 4];
    const float* b2   = (const float*)d_in[wi + 5];
    float* out = (float*)d_out;

    fno_decode_gemm<<<dim3(DECM / 128, B / 8), 128>>>(token, wdec, bdec);
    fno_build_R<<<B, 256>>>(w1);
    fno_main<<<dim3((LOUT + 255) / 256, B), 256>>>(b1, w2, b2, out);
}

// round 2
// speedup vs baseline: 1.2920x; 1.2920x over previous
#include <cuda_runtime.h>
#include <math.h>

// Problem constants (fixed shapes)
#define B      64
#define EMB    1024
#define WID    64
#define MODES  16
#define LSEQ   8192
#define LOUT   8190       // LSEQ - PADDING(2)
#define NH     128        // hidden width of MLP
#define DECM   2048       // WID*MODES*2
#define KS     8          // split-K slices in kernel 1

// Scratch (allocation-free rule: __device__ globals)
__device__ float  g_Hp[KS][B][DECM];      // split-K partials of token @ w_dec
__device__ float4 g_R[B * NH * 8];        // interleaved (P,Q) coeffs [B][128 j][16k*2]

// ---------------------------------------------------------------------------
// Kernel 1: split-K GEMM  Hp[ks] = token[:, k-slice] @ w_dec[k-slice, :]
// grid (DECM/128 = 16 n-tiles, KS=8), block 256.
// Each thread: one n column, 32 m-rows (mhalf selects which 32 of 64).
// ---------------------------------------------------------------------------
__global__ void __launch_bounds__(256) fno_decode_gemm(
    const float* __restrict__ token,   // [B][EMB]
    const float* __restrict__ wdec)    // [EMB][DECM]
{
    __shared__ float4 Ts4[B][32];      // token tile [m][kk/4], 32 KB

    const int n     = blockIdx.x * 128 + (threadIdx.x & 127);
    const int mhalf = threadIdx.x >> 7;            // 0 or 1
    const int k0    = blockIdx.y * 128;

    // load token tile: coalesced float4 reads, conflict-free writes
    const float4* tok4 = (const float4*)token;
    for (int i = threadIdx.x; i < B * 32; i += 256) {
        int m = i >> 5, q = i & 31;
        Ts4[m][q] = tok4[m * (EMB / 4) + (k0 >> 2) + q];
    }
    __syncthreads();

    float acc[32];
#pragma unroll
    for (int mm = 0; mm < 32; mm++) acc[mm] = 0.f;

#pragma unroll 2
    for (int kk4 = 0; kk4 < 32; kk4++) {
        const int kg = k0 + kk4 * 4;
        const float w0 = wdec[(kg + 0) * DECM + n];
        const float w1_ = wdec[(kg + 1) * DECM + n];
        const float w2_ = wdec[(kg + 2) * DECM + n];
        const float w3_ = wdec[(kg + 3) * DECM + n];
#pragma unroll
        for (int mm = 0; mm < 32; mm++) {
            float4 t = Ts4[mhalf * 32 + mm][kk4];   // warp-broadcast LDS.128
            float a = acc[mm];
            a = fmaf(t.x, w0, a);
            a = fmaf(t.y, w1_, a);
            a = fmaf(t.z, w2_, a);
            a = fmaf(t.w, w3_, a);
            acc[mm] = a;
        }
    }

#pragma unroll
    for (int mm = 0; mm < 32; mm++)
        g_Hp[blockIdx.y][mhalf * 32 + mm][n] = acc[mm];
}

// ---------------------------------------------------------------------------
// Kernel 2: reduce split-K partials + bias, then build spectral->hidden coeffs
//   P[b,j,k] = sA(k) * sum_w w1[w,j] * H[b,w,k,re]
//   Q[b,j,k] = sB(k) * sum_w w1[w,j] * H[b,w,k,im]
// grid 64 (one b), 256 threads
// ---------------------------------------------------------------------------
__global__ void __launch_bounds__(256) fno_build_R(
    const float* __restrict__ w1,      // [WID][NH]
    const float* __restrict__ bdec)    // [DECM]
{
    __shared__ float w1s[WID * NH];    // 32 KB
    __shared__ float Hs[DECM];         // 8 KB  ([w][k][2])
    const int b = blockIdx.x;

    for (int i = threadIdx.x; i < WID * NH; i += 256) w1s[i] = w1[i];
    for (int i = threadIdx.x; i < DECM; i += 256) {
        float h = bdec[i];
#pragma unroll
        for (int ks = 0; ks < KS; ks++) h += g_Hp[ks][b][i];
        Hs[i] = h;
    }
    __syncthreads();

    const float inv = 1.0f / (float)LSEQ;
    float* Rf = (float*)g_R;

    for (int c = threadIdx.x; c < NH * MODES; c += 256) {
        int j = c >> 4;
        int k = c & 15;
        float P = 0.f, Q = 0.f;
#pragma unroll 8
        for (int w = 0; w < WID; w++) {
            float a = w1s[w * NH + j];
            P = fmaf(a, Hs[w * 32 + 2 * k],     P);
            Q = fmaf(a, Hs[w * 32 + 2 * k + 1], Q);
        }
        float sA = (k == 0) ? inv : 2.0f * inv;
        float sB = (k == 0) ? 0.f : -2.0f * inv;
        Rf[(b * NH + j) * 32 + 2 * k]     = sA * P;
        Rf[(b * NH + j) * 32 + 2 * k + 1] = sB * Q;
    }
}

// ---------------------------------------------------------------------------
// Kernel 3 (hot): two output positions per thread (l and l+256)
//   h1[j] = b1[j] + sum_k P[j,k] cos(th_k l) + Q[j,k] sin(th_k l)
//   out   = b2 + sum_j gelu_erf(h1[j]) * w2[j]
// Second position's trig from a constant rotation by Delta=256 (th_k*256 = pi*k/16).
// grid (16 l-chunks of 512, 64 b), 256 threads
// ---------------------------------------------------------------------------
__global__ void __launch_bounds__(256) fno_main(
    const float* __restrict__ b1,
    const float* __restrict__ w2,
    const float* __restrict__ b2,
    float* __restrict__ out)
{
    __shared__ float4 Rs[NH * 8];      // 16 KB
    __shared__ float  b1s[NH], w2s[NH];

    const int b = blockIdx.y;
    const float4* Rg = g_R + b * NH * 8;
    for (int i = threadIdx.x; i < NH * 8; i += 256) Rs[i] = Rg[i];
    if (threadIdx.x < NH) {
        b1s[threadIdx.x] = b1[threadIdx.x];
        w2s[threadIdx.x] = w2[threadIdx.x];
    }
    __syncthreads();

    const int l = blockIdx.x * 512 + threadIdx.x;   // second pos: l + 256

    // trig for position l via one sincos + Chebyshev recurrence
    float c[MODES], s[MODES], c2[MODES], s2[MODES];
    float ang = (float)l * 7.6699039394282067e-4f;  // 2*pi/8192
    float s1, c1;
    sincosf(ang, &s1, &c1);
    c[0] = 1.f; s[0] = 0.f;
    c[1] = c1;  s[1] = s1;
    const float t2 = 2.f * c1;
#pragma unroll
    for (int k = 2; k < MODES; k++) {
        c[k] = fmaf(t2, c[k - 1], -c[k - 2]);
        s[k] = fmaf(t2, s[k - 1], -s[k - 2]);
    }
    // rotate by Delta = 256: theta_k*256 = pi*k/16 (compile-time constants)
    const float CK[MODES] = {
        1.f, 0.980785280403230f, 0.923879532511287f, 0.831469612302545f,
        0.707106781186548f, 0.555570233019602f, 0.382683432365090f, 0.195090322016128f,
        0.f, -0.195090322016128f, -0.382683432365090f, -0.555570233019602f,
        -0.707106781186548f, -0.831469612302545f, -0.923879532511287f, -0.980785280403230f};
    const float SK[MODES] = {
        0.f, 0.195090322016128f, 0.382683432365090f, 0.555570233019602f,
        0.707106781186548f, 0.831469612302545f, 0.923879532511287f, 0.980785280403230f,
        1.f, 0.980785280403230f, 0.923879532511287f, 0.831469612302545f,
        0.707106781186548f, 0.555570233019602f, 0.382683432365090f, 0.195090322016128f};
#pragma unroll
    for (int k = 0; k < MODES; k++) {
        c2[k] = c[k] * CK[k] - s[k] * SK[k];
        s2[k] = fmaf(s[k], CK[k], c[k] * SK[k]);
    }

    float acc1 = 0.f, acc2 = 0.f;
#pragma unroll 2
    for (int j = 0; j < NH; j++) {
        float h1 = b1s[j], h2 = h1;
        const float4* rj = &Rs[j * 8];
#pragma unroll
        for (int kp = 0; kp < 8; kp++) {
            float4 r = rj[kp];                    // broadcast LDS.128, shared by both l's
            h1 = fmaf(r.x, c[2 * kp],      h1);
            h1 = fmaf(r.y, s[2 * kp],      h1);
            h1 = fmaf(r.z, c[2 * kp + 1],  h1);
            h1 = fmaf(r.w, s[2 * kp + 1],  h1);
            h2 = fmaf(r.x, c2[2 * kp],     h2);
            h2 = fmaf(r.y, s2[2 * kp],     h2);
            h2 = fmaf(r.z, c2[2 * kp + 1], h2);
            h2 = fmaf(r.w, s2[2 * kp + 1], h2);
        }
        float g1 = 0.5f * h1 * (1.0f + erff(h1 * 0.70710678118654752f));
        float g2 = 0.5f * h2 * (1.0f + erff(h2 * 0.70710678118654752f));
        acc1 = fmaf(g1, w2s[j], acc1);
        acc2 = fmaf(g2, w2s[j], acc2);
    }
    float bias2 = b2[0];
    if (l < LOUT)        out[b * LOUT + l]        = acc1 + bias2;
    if (l + 256 < LOUT)  out[b * LOUT + l + 256]  = acc2 + bias2;
}

// ---------------------------------------------------------------------------
extern "C" void kernel_launch(void* const* d_in, const int* in_sizes, int n_in,
                              void* d_out, int out_size)
{
    // inputs: token, [x_len], w_dec, b_dec, w1, b1, w2, b2
    const float* token = (const float*)d_in[0];
    int wi = (in_sizes[1] < 100) ? 2 : 1;   // skip x_len scalar if present
    const float* wdec = (const float*)d_in[wi + 0];
    const float* bdec = (const float*)d_in[wi + 1];
    const float* w1   = (const float*)d_in[wi + 2];
    const float* b1   = (const float*)d_in[wi + 3];
    const float* w2   = (const float*)d_in[wi + 4];
    const float* b2   = (const float*)d_in[wi + 5];
    float* out = (float*)d_out;

    fno_decode_gemm<<<dim3(DECM / 128, KS), 256>>>(token, wdec);
    fno_build_R<<<B, 256>>>(w1, bdec);
    fno_main<<<dim3(16, B), 256>>>(b1, w2, b2, out);
}

// round 3
// speedup vs baseline: 1.7879x; 1.3838x over previous
#include <cuda_runtime.h>
#include <math.h>

// Problem constants (fixed shapes)
#define B      64
#define EMB    1024
#define WID    64
#define MODES  16
#define LSEQ   8192
#define LOUT   8190       // LSEQ - PADDING(2)
#define NH     128        // hidden width of MLP
#define DECM   2048       // WID*MODES*2
#define KS     32         // split-K slices in kernel 1
#define KSL    32         // k per slice (EMB/KS)

typedef unsigned long long u64;

// Scratch (allocation-free rule: __device__ globals)
__device__ float  g_Hp[KS][B][DECM];      // split-K partials (16 MB, L2-resident)
__device__ float  g_H[B][DECM];           // reduced H
__device__ float4 g_R[B * NH * 8];        // interleaved (P,Q) coeffs [B][128 j][16 modes *2]

// ---- packed f32x2 helpers (Blackwell FFMA2) --------------------------------
__device__ __forceinline__ u64 pk2(float lo, float hi) {
    u64 r; asm("mov.b64 %0, {%1,%2};" : "=l"(r) : "f"(lo), "f"(hi)); return r;
}
__device__ __forceinline__ void upk2(u64 v, float& lo, float& hi) {
    asm("mov.b64 {%0,%1}, %2;" : "=f"(lo), "=f"(hi) : "l"(v));
}
__device__ __forceinline__ u64 ffma2(u64 a, u64 b, u64 c) {
    u64 d; asm("fma.rn.f32x2 %0, %1, %2, %3;" : "=l"(d) : "l"(a), "l"(b), "l"(c)); return d;
}
__device__ __forceinline__ u64 fmul2(u64 a, u64 b) {
    u64 d; asm("mul.rn.f32x2 %0, %1, %2;" : "=l"(d) : "l"(a), "l"(b)); return d;
}

// ---------------------------------------------------------------------------
// Kernel 1: split-K GEMM  Hp[ks] = token[:, slice] @ w_dec[slice, :]
// grid (16 n-tiles, 32 k-slices) = 512 CTAs, 256 threads.
// ---------------------------------------------------------------------------
__global__ void __launch_bounds__(256) fno_decode_gemm(
    const float* __restrict__ token,   // [B][EMB]
    const float* __restrict__ wdec)    // [EMB][DECM]
{
    __shared__ float4 Ts4[B][KSL / 4];   // 8 KB token tile

    const int n     = blockIdx.x * 128 + (threadIdx.x & 127);
    const int mhalf = threadIdx.x >> 7;
    const int k0    = blockIdx.y * KSL;

    const float4* tok4 = (const float4*)token;
    for (int i = threadIdx.x; i < B * (KSL / 4); i += 256) {
        int m = i >> 3, q = i & 7;
        Ts4[m][q] = tok4[m * (EMB / 4) + (k0 >> 2) + q];
    }
    __syncthreads();

    float acc[32];
#pragma unroll
    for (int mm = 0; mm < 32; mm++) acc[mm] = 0.f;

#pragma unroll
    for (int kk4 = 0; kk4 < KSL / 4; kk4++) {
        const int kg = k0 + kk4 * 4;
        const float w0 = wdec[(kg + 0) * DECM + n];
        const float w1_ = wdec[(kg + 1) * DECM + n];
        const float w2_ = wdec[(kg + 2) * DECM + n];
        const float w3_ = wdec[(kg + 3) * DECM + n];
#pragma unroll
        for (int mm = 0; mm < 32; mm++) {
            float4 t = Ts4[mhalf * 32 + mm][kk4];   // warp-broadcast LDS.128
            float a = acc[mm];
            a = fmaf(t.x, w0, a);
            a = fmaf(t.y, w1_, a);
            a = fmaf(t.z, w2_, a);
            a = fmaf(t.w, w3_, a);
            acc[mm] = a;
        }
    }
#pragma unroll
    for (int mm = 0; mm < 32; mm++)
        g_Hp[blockIdx.y][mhalf * 32 + mm][n] = acc[mm];
}

// ---------------------------------------------------------------------------
// Kernel 1b: reduce split-K partials + bias -> g_H
// grid 256, 256 threads; 2 elems/thread, 32 coalesced loads each.
// ---------------------------------------------------------------------------
__global__ void __launch_bounds__(256) fno_reduce(
    const float* __restrict__ bdec)
{
    const int base = (blockIdx.x * 256 + threadIdx.x) * 2;
    // base < B*DECM = 131072; grid*block*2 = 131072 exactly
    const int b0 = base / DECM, i0 = base % DECM;
    float h0 = bdec[i0], h1 = bdec[i0 + 1];
#pragma unroll
    for (int ks = 0; ks < KS; ks++) {
        h0 += g_Hp[ks][b0][i0];
        h1 += g_Hp[ks][b0][i0 + 1];
    }
    g_H[b0][i0]     = h0;
    g_H[b0][i0 + 1] = h1;
}

// ---------------------------------------------------------------------------
// Kernel 2: build spectral->hidden coefficients
//   P[b,j,k] = sA(k) * sum_w w1[w,j] * H[b,w,k,re]
//   Q[b,j,k] = sB(k) * sum_w w1[w,j] * H[b,w,k,im]
// grid (64 b, 8 j-chunks of 16) = 512 CTAs, 128 threads.
// ---------------------------------------------------------------------------
__global__ void __launch_bounds__(128) fno_build_R(
    const float* __restrict__ w1)      // [WID][NH]
{
    __shared__ float Hs[DECM];         // 8 KB  [w][k][2]
    __shared__ float w1s[WID][16];     // 4 KB  slice of w1
    const int b  = blockIdx.x;
    const int j0 = blockIdx.y * 16;

    for (int i = threadIdx.x; i < DECM; i += 128) Hs[i] = g_H[b][i];
    for (int i = threadIdx.x; i < WID * 16; i += 128) {
        int w = i >> 4, jj = i & 15;
        w1s[w][jj] = w1[w * NH + j0 + jj];
    }
    __syncthreads();

    const float inv = 1.0f / (float)LSEQ;
    float* Rf = (float*)g_R;

    // 256 (j,k) pairs per CTA, 2 per thread
#pragma unroll
    for (int q = 0; q < 2; q++) {
        int c  = threadIdx.x + q * 128;
        int jj = c >> 4;
        int k  = c & 15;
        float P = 0.f, Q = 0.f;
#pragma unroll 8
        for (int w = 0; w < WID; w++) {
            float a = w1s[w][jj];
            P = fmaf(a, Hs[w * 32 + 2 * k],     P);
            Q = fmaf(a, Hs[w * 32 + 2 * k + 1], Q);
        }
        float sA = (k == 0) ? inv : 2.0f * inv;
        float sB = (k == 0) ? 0.f : -2.0f * inv;
        int j = j0 + jj;
        Rf[(b * NH + j) * 32 + 2 * k]     = sA * P;
        Rf[(b * NH + j) * 32 + 2 * k + 1] = sB * Q;
    }
}

// ---------------------------------------------------------------------------
// Kernel 3 (hot): positions l and l+4096 per thread.
//   theta_k*(l+4096) = theta_k*l + pi*k  ->  term flips by (-1)^k.
//   Accumulate even-k (he) / odd-k (ho) sums packed as f32x2 (cos-part, sin-part):
//     h(l) = he+ho, h(l+4096) = he-ho   -- second position is FREE.
// grid (16 l-chunks, 64 b), 256 threads.
// ---------------------------------------------------------------------------
__global__ void __launch_bounds__(256) fno_main(
    const float* __restrict__ b1,
    const float* __restrict__ w2,
    const float* __restrict__ b2,
    float* __restrict__ out)
{
    __shared__ float4 Rs[NH * 8];      // 16 KB, packed (P,Q) pairs per mode
    __shared__ float  b1s[NH], w2s[NH];

    const int b = blockIdx.y;
    const float4* Rg = g_R + b * NH * 8;
    for (int i = threadIdx.x; i < NH * 8; i += 256) Rs[i] = Rg[i];
    if (threadIdx.x < NH) {
        b1s[threadIdx.x] = b1[threadIdx.x];
        w2s[threadIdx.x] = w2[threadIdx.x];
    }
    __syncthreads();

    const int l = blockIdx.x * 256 + threadIdx.x;   // [0, 4096)

    // trig via one sincos + Chebyshev recurrence, packed (c,s) per mode
    float c[MODES], s[MODES];
    float ang = (float)l * 7.6699039394282067e-4f;  // 2*pi/8192
    float s1, c1;
    sincosf(ang, &s1, &c1);
    c[0] = 1.f; s[0] = 0.f;
    c[1] = c1;  s[1] = s1;
    const float t2 = 2.f * c1;
#pragma unroll
    for (int k = 2; k < MODES; k++) {
        c[k] = fmaf(t2, c[k - 1], -c[k - 2]);
        s[k] = fmaf(t2, s[k - 1], -s[k - 2]);
    }
    u64 cs[MODES];
#pragma unroll
    for (int k = 0; k < MODES; k++) cs[k] = pk2(c[k], s[k]);

    float acc1 = 0.f, acc2 = 0.f;
#pragma unroll 2
    for (int j = 0; j < NH; j++) {
        const ulonglong2* rj = (const ulonglong2*)(Rs + j * 8);
        ulonglong2 r0 = rj[0];                    // ld.shared.v2.u64
        u64 he = fmul2(r0.x, cs[0]);              // even modes
        u64 ho = fmul2(r0.y, cs[1]);              // odd modes
#pragma unroll
        for (int kp = 1; kp < 8; kp++) {
            ulonglong2 rr = rj[kp];
            he = ffma2(rr.x, cs[2 * kp],     he);
            ho = ffma2(rr.y, cs[2 * kp + 1], ho);
        }
        float e0, e1, o0, o1;
        upk2(he, e0, e1);
        upk2(ho, o0, o1);
        float base = b1s[j];
        float e = e0 + e1, o = o0 + o1;
        float h1 = base + e + o;
        float h2 = base + e - o;
        float g1 = 0.5f * h1 * (1.0f + erff(h1 * 0.70710678118654752f));
        float g2 = 0.5f * h2 * (1.0f + erff(h2 * 0.70710678118654752f));
        float wj = w2s[j];
        acc1 = fmaf(g1, wj, acc1);
        acc2 = fmaf(g2, wj, acc2);
    }
    float bias2 = b2[0];
    out[b * LOUT + l] = acc1 + bias2;             // l < 4096 always valid
    if (l + 4096 < LOUT) out[b * LOUT + l + 4096] = acc2 + bias2;
}

// ---------------------------------------------------------------------------
extern "C" void kernel_launch(void* const* d_in, const int* in_sizes, int n_in,
                              void* d_out, int out_size)
{
    // inputs: token, [x_len], w_dec, b_dec, w1, b1, w2, b2
    const float* token = (const float*)d_in[0];
    int wi = (in_sizes[1] < 100) ? 2 : 1;   // skip x_len scalar if present
    const float* wdec = (const float*)d_in[wi + 0];
    const float* bdec = (const float*)d_in[wi + 1];
    const float* w1   = (const float*)d_in[wi + 2];
    const float* b1   = (const float*)d_in[wi + 3];
    const float* w2   = (const float*)d_in[wi + 4];
    const float* b2   = (const float*)d_in[wi + 5];
    float* out = (float*)d_out;

    fno_decode_gemm<<<dim3(DECM / 128, KS), 256>>>(token, wdec);
    fno_reduce<<<B * DECM / 512, 256>>>(bdec);
    fno_build_R<<<dim3(B, 8), 128>>>(w1);
    fno_main<<<dim3(16, B), 256>>>(b1, w2, b2, out);
}

// round 4
// speedup vs baseline: 1.8453x; 1.0321x over previous
#include <cuda_runtime.h>
#include <math.h>

// Problem constants (fixed shapes)
#define B      64
#define EMB    1024
#define WID    64
#define MODES  16
#define LSEQ   8192
#define LOUT   8190       // LSEQ - PADDING(2)
#define NH     128        // hidden width of MLP
#define DECM   2048       // WID*MODES*2
#define KS     32         // split-K slices in kernel 1
#define KSL    32         // k per slice (EMB/KS)

typedef unsigned long long u64;

// Scratch (allocation-free rule: __device__ globals)
__device__ float  g_Hp[KS][B][DECM];      // split-K partials (16 MB, L2-resident)
__device__ float  g_H[B][DECM];           // reduced H
__device__ float4 g_R[B * NH * 8];        // interleaved (P,Q) coeffs [B][128 j][16 modes *2]

// ---- packed f32x2 helpers (Blackwell FFMA2) --------------------------------
__device__ __forceinline__ u64 pk2(float lo, float hi) {
    u64 r; asm("mov.b64 %0, {%1,%2};" : "=l"(r) : "f"(lo), "f"(hi)); return r;
}
__device__ __forceinline__ void upk2(u64 v, float& lo, float& hi) {
    asm("mov.b64 {%0,%1}, %2;" : "=f"(lo), "=f"(hi) : "l"(v));
}
__device__ __forceinline__ u64 ffma2(u64 a, u64 b, u64 c) {
    u64 d; asm("fma.rn.f32x2 %0, %1, %2, %3;" : "=l"(d) : "l"(a), "l"(b), "l"(c)); return d;
}
__device__ __forceinline__ u64 fmul2(u64 a, u64 b) {
    u64 d; asm("mul.rn.f32x2 %0, %1, %2;" : "=l"(d) : "l"(a), "l"(b)); return d;
}

// ---------------------------------------------------------------------------
// Kernel 1: split-K GEMM  Hp[ks] = token[:, slice] @ w_dec[slice, :]
// grid (16 n-tiles, 32 k-slices) = 512 CTAs, 256 threads.
// ---------------------------------------------------------------------------
__global__ void __launch_bounds__(256) fno_decode_gemm(
    const float* __restrict__ token,   // [B][EMB]
    const float* __restrict__ wdec)    // [EMB][DECM]
{
    __shared__ float4 Ts4[B][KSL / 4];   // 8 KB token tile

    const int n     = blockIdx.x * 128 + (threadIdx.x & 127);
    const int mhalf = threadIdx.x >> 7;
    const int k0    = blockIdx.y * KSL;

    const float4* tok4 = (const float4*)token;
    for (int i = threadIdx.x; i < B * (KSL / 4); i += 256) {
        int m = i >> 3, q = i & 7;
        Ts4[m][q] = tok4[m * (EMB / 4) + (k0 >> 2) + q];
    }
    __syncthreads();

    float acc[32];
#pragma unroll
    for (int mm = 0; mm < 32; mm++) acc[mm] = 0.f;

#pragma unroll
    for (int kk4 = 0; kk4 < KSL / 4; kk4++) {
        const int kg = k0 + kk4 * 4;
        const float w0 = wdec[(kg + 0) * DECM + n];
        const float w1_ = wdec[(kg + 1) * DECM + n];
        const float w2_ = wdec[(kg + 2) * DECM + n];
        const float w3_ = wdec[(kg + 3) * DECM + n];
#pragma unroll
        for (int mm = 0; mm < 32; mm++) {
            float4 t = Ts4[mhalf * 32 + mm][kk4];   // warp-broadcast LDS.128
            float a = acc[mm];
            a = fmaf(t.x, w0, a);
            a = fmaf(t.y, w1_, a);
            a = fmaf(t.z, w2_, a);
            a = fmaf(t.w, w3_, a);
            acc[mm] = a;
        }
    }
#pragma unroll
    for (int mm = 0; mm < 32; mm++)
        g_Hp[blockIdx.y][mhalf * 32 + mm][n] = acc[mm];
}

// ---------------------------------------------------------------------------
// Kernel 1b: reduce split-K partials + bias -> g_H
// ---------------------------------------------------------------------------
__global__ void __launch_bounds__(256) fno_reduce(
    const float* __restrict__ bdec)
{
    const int base = (blockIdx.x * 256 + threadIdx.x) * 2;
    const int b0 = base / DECM, i0 = base % DECM;
    float h0 = bdec[i0], h1 = bdec[i0 + 1];
#pragma unroll
    for (int ks = 0; ks < KS; ks++) {
        h0 += g_Hp[ks][b0][i0];
        h1 += g_Hp[ks][b0][i0 + 1];
    }
    g_H[b0][i0]     = h0;
    g_H[b0][i0 + 1] = h1;
}

// ---------------------------------------------------------------------------
// Kernel 2: build spectral->hidden coefficients
// grid (64 b, 8 j-chunks of 16), 128 threads.
// ---------------------------------------------------------------------------
__global__ void __launch_bounds__(128) fno_build_R(
    const float* __restrict__ w1)      // [WID][NH]
{
    __shared__ float Hs[DECM];         // 8 KB  [w][k][2]
    __shared__ float w1s[WID][16];     // 4 KB
    const int b  = blockIdx.x;
    const int j0 = blockIdx.y * 16;

    for (int i = threadIdx.x; i < DECM; i += 128) Hs[i] = g_H[b][i];
    for (int i = threadIdx.x; i < WID * 16; i += 128) {
        int w = i >> 4, jj = i & 15;
        w1s[w][jj] = w1[w * NH + j0 + jj];
    }
    __syncthreads();

    const float inv = 1.0f / (float)LSEQ;
    float* Rf = (float*)g_R;

#pragma unroll
    for (int q = 0; q < 2; q++) {
        int c  = threadIdx.x + q * 128;
        int jj = c >> 4;
        int k  = c & 15;
        float P = 0.f, Q = 0.f;
#pragma unroll 8
        for (int w = 0; w < WID; w++) {
            float a = w1s[w][jj];
            P = fmaf(a, Hs[w * 32 + 2 * k],     P);
            Q = fmaf(a, Hs[w * 32 + 2 * k + 1], Q);
        }
        float sA = (k == 0) ? inv : 2.0f * inv;
        float sB = (k == 0) ? 0.f : -2.0f * inv;
        int j = j0 + jj;
        Rf[(b * NH + j) * 32 + 2 * k]     = sA * P;
        Rf[(b * NH + j) * 32 + 2 * k + 1] = sB * Q;
    }
}

// ---------------------------------------------------------------------------
// Kernel 3 (hot): FOUR positions per thread via trig symmetry.
//   t in [0,2048]; positions { t, 4096-t, 4096+t, 8192-t } share (c_k, s_k):
//     at 4096±t odd-k terms negate; at (4096-t, 8192-t) sin-part negates.
//   Two packed f32x2 accumulators (even/odd k) of (Sum P*c, Sum Q*s):
//     one FFMA2 per mode serves all four positions.
//   h(t)      = b + (ePc+eQs) + (oPc+oQs)
//   h(4096+t) = b + (ePc+eQs) - (oPc+oQs)
//   h(8192-t) = b + (ePc-eQs) + (oPc-oQs)
//   h(4096-t) = b + (ePc-eQs) - (oPc-oQs)
// grid (9 chunks, 64 b), 256 threads; t>2048 idle.
// ---------------------------------------------------------------------------
__global__ void __launch_bounds__(256) fno_main(
    const float* __restrict__ b1,
    const float* __restrict__ w2,
    const float* __restrict__ b2,
    float* __restrict__ out)
{
    __shared__ float4 Rs[NH * 8];      // 16 KB, (P,Q) pairs per mode
    __shared__ float  b1s[NH], w2s[NH];

    const int b = blockIdx.y;
    const float4* Rg = g_R + b * NH * 8;
    for (int i = threadIdx.x; i < NH * 8; i += 256) Rs[i] = Rg[i];
    if (threadIdx.x < NH) {
        b1s[threadIdx.x] = b1[threadIdx.x];
        w2s[threadIdx.x] = w2[threadIdx.x];
    }
    __syncthreads();

    const int t = blockIdx.x * 256 + threadIdx.x;
    if (t > 2048) return;

    // trig via one sincos + Chebyshev recurrence, packed (c,s) per mode
    float c[MODES], s[MODES];
    float ang = (float)t * 7.6699039394282067e-4f;  // 2*pi/8192
    float s1, c1;
    sincosf(ang, &s1, &c1);
    c[0] = 1.f; s[0] = 0.f;
    c[1] = c1;  s[1] = s1;
    const float t2 = 2.f * c1;
#pragma unroll
    for (int k = 2; k < MODES; k++) {
        c[k] = fmaf(t2, c[k - 1], -c[k - 2]);
        s[k] = fmaf(t2, s[k - 1], -s[k - 2]);
    }
    u64 cs[MODES];
#pragma unroll
    for (int k = 0; k < MODES; k++) cs[k] = pk2(c[k], s[k]);

    float acc1 = 0.f, acc2 = 0.f, acc3 = 0.f, acc4 = 0.f;
#pragma unroll 2
    for (int j = 0; j < NH; j++) {
        const ulonglong2* rj = (const ulonglong2*)(Rs + j * 8);
        ulonglong2 r0 = rj[0];                    // ld.shared.v2.u64 (broadcast)
        u64 e = fmul2(r0.x, cs[0]);               // even modes: (Sum P*c, Sum Q*s)
        u64 o = fmul2(r0.y, cs[1]);               // odd modes
#pragma unroll
        for (int kp = 1; kp < 8; kp++) {
            ulonglong2 rr = rj[kp];
            e = ffma2(rr.x, cs[2 * kp],     e);
            o = ffma2(rr.y, cs[2 * kp + 1], o);
        }
        float ePc, eQs, oPc, oQs;
        upk2(e, ePc, eQs);
        upk2(o, oPc, oQs);
        const float bb = b1s[j];
        float S1 = ePc + eQs, S2 = oPc + oQs;
        float S3 = ePc - eQs, S4 = oPc - oQs;
        float hA = bb + S1;
        float hB = bb + S3;
        float h1 = hA + S2;   // pos t
        float h3 = hA - S2;   // pos 4096+t
        float h4 = hB + S4;   // pos 8192-t
        float h2 = hB - S4;   // pos 4096-t
        float g1 = 0.5f * h1 * (1.0f + erff(h1 * 0.70710678118654752f));
        float g2 = 0.5f * h2 * (1.0f + erff(h2 * 0.70710678118654752f));
        float g3 = 0.5f * h3 * (1.0f + erff(h3 * 0.70710678118654752f));
        float g4 = 0.5f * h4 * (1.0f + erff(h4 * 0.70710678118654752f));
        const float wj = w2s[j];
        acc1 = fmaf(g1, wj, acc1);
        acc2 = fmaf(g2, wj, acc2);
        acc3 = fmaf(g3, wj, acc3);
        acc4 = fmaf(g4, wj, acc4);
    }
    const float bias2 = b2[0];
    float* ob = out + b * LOUT;
    ob[t] = acc1 + bias2;                                   // 0..2048
    if (t > 0 && t < 2048) ob[4096 - t] = acc2 + bias2;     // 2049..4095
    ob[4096 + t] = acc3 + bias2;                            // 4096..6144
    if (t > 2 && t < 2048) ob[8192 - t] = acc4 + bias2;     // 6145..8189
}

// ---------------------------------------------------------------------------
extern "C" void kernel_launch(void* const* d_in, const int* in_sizes, int n_in,
                              void* d_out, int out_size)
{
    // inputs: token, [x_len], w_dec, b_dec, w1, b1, w2, b2
    const float* token = (const float*)d_in[0];
    int wi = (in_sizes[1] < 100) ? 2 : 1;   // skip x_len scalar if present
    const float* wdec = (const float*)d_in[wi + 0];
    const float* bdec = (const float*)d_in[wi + 1];
    const float* w1   = (const float*)d_in[wi + 2];
    const float* b1   = (const float*)d_in[wi + 3];
    const float* w2   = (const float*)d_in[wi + 4];
    const float* b2   = (const float*)d_in[wi + 5];
    float* out = (float*)d_out;

    fno_decode_gemm<<<dim3(DECM / 128, KS), 256>>>(token, wdec);
    fno_reduce<<<B * DECM / 512, 256>>>(bdec);
    fno_build_R<<<dim3(B, 8), 128>>>(w1);
    fno_main<<<dim3(9, B), 256>>>(b1, w2, b2, out);
}